// round 1
// baseline (speedup 1.0000x reference)
#include <cuda_runtime.h>
#include <math.h>

// AttentionAggregator: sparse reformulation.
// features: [100000, 256] f32; nodes: [4096] i32; unique_ids: [16384] i32;
// neigh_idx: [4096, 10] i32. out: [4096, 256] f32.
//
// Per row: softmax over <=10 (deduplicated) neighbor dot products, then
// weighted sum of those embed rows. All masked columns are exactly 0 after
// softmax (exp(-9e15 - max) == 0 in fp32), so this matches the dense ref.

#define N_NODES 4096
#define FDIM    256
#define NSAMP   10

__global__ __launch_bounds__(320, 4)
void attn_agg_kernel(const float* __restrict__ feat,
                     const int*   __restrict__ nodes,
                     const int*   __restrict__ uids,
                     const int*   __restrict__ nidx,
                     float*       __restrict__ out)
{
    const int row  = blockIdx.x;
    const int tid  = threadIdx.x;
    const int warp = tid >> 5;
    const int lane = tid & 31;

    __shared__ float qf[FDIM];      // node feature row
    __shared__ int   cols[NSAMP];   // neigh columns
    __shared__ int   suid[NSAMP];   // vocab ids of neighbors
    __shared__ float dots[NSAMP];
    __shared__ float w[NSAMP];      // softmax weights (0 for dups)

    // Phase 0: load node feature row + neighbor columns
    const int node = nodes[row];
    if (tid < FDIM) qf[tid] = feat[(size_t)node * FDIM + tid];
    if (tid < NSAMP) cols[tid] = nidx[row * NSAMP + tid];
    __syncthreads();

    // Phase 1: warp s computes dot(q, embed[cols[s]]) over 256 dims.
    // float4 loads: lane reads v4[lane] and v4[lane+32] -> 2x LDG.128, coalesced.
    {
        const int c   = cols[warp];
        const int uid = uids[c];
        if (lane == 0) suid[warp] = uid;
        const float4* er4 = (const float4*)(feat + (size_t)uid * FDIM);
        const float4* qf4 = (const float4*)qf;
        float4 a0 = er4[lane];
        float4 a1 = er4[lane + 32];
        float4 q0 = qf4[lane];
        float4 q1 = qf4[lane + 32];
        float acc = a0.x * q0.x + a0.y * q0.y + a0.z * q0.z + a0.w * q0.w
                  + a1.x * q1.x + a1.y * q1.y + a1.z * q1.z + a1.w * q1.w;
        #pragma unroll
        for (int o = 16; o; o >>= 1)
            acc += __shfl_xor_sync(0xffffffffu, acc, o);
        if (lane == 0) dots[warp] = acc;
    }
    __syncthreads();

    // Phase 2: thread 0 dedups columns and computes softmax over distinct set.
    // Duplicate (row, col) pairs appear once in the dense mask -> count once.
    if (tid == 0) {
        bool dup[NSAMP];
        float m = -INFINITY;
        #pragma unroll
        for (int s = 0; s < NSAMP; s++) {
            bool d = false;
            for (int t = 0; t < s; t++) d |= (cols[t] == cols[s]);
            dup[s] = d;
            if (!d) m = fmaxf(m, dots[s]);
        }
        float sum = 0.f;
        #pragma unroll
        for (int s = 0; s < NSAMP; s++) {
            float e = dup[s] ? 0.f : __expf(dots[s] - m);
            w[s] = e;
            sum += e;
        }
        float inv = 1.f / sum;
        #pragma unroll
        for (int s = 0; s < NSAMP; s++) w[s] *= inv;
    }
    __syncthreads();

    // Phase 3: threads 0..255 accumulate out[row, f] = sum_s w[s]*embed[s][f].
    // Embed rows are L1/L2-hot from phase 1.
    if (tid < FDIM) {
        float acc = 0.f;
        #pragma unroll
        for (int s = 0; s < NSAMP; s++) {
            const float ws = w[s];
            if (ws != 0.f)
                acc += ws * feat[(size_t)suid[s] * FDIM + tid];
        }
        out[(size_t)row * FDIM + tid] = acc;
    }
}

extern "C" void kernel_launch(void* const* d_in, const int* in_sizes, int n_in,
                              void* d_out, int out_size)
{
    const float* feat  = (const float*)d_in[0];
    const int*   nodes = (const int*)  d_in[1];
    const int*   uids  = (const int*)  d_in[2];
    const int*   nidx  = (const int*)  d_in[3];
    float*       out   = (float*)d_out;
    (void)in_sizes; (void)n_in; (void)out_size;

    attn_agg_kernel<<<N_NODES, 320>>>(feat, nodes, uids, nidx, out);
}